// round 2
// baseline (speedup 1.0000x reference)
#include <cuda_runtime.h>
#include <math.h>

#define BATCH 64
#define SEQ   512
#define EMB   256
#define HID   512
#define G4    2048   // 4*HID
#define NCLS  4

// Scratch (allocation-free rule: __device__ globals)
__device__ float g_xg[(size_t)SEQ * BATCH * G4];   // [T][B][4H], 256 MiB
__device__ float g_h[2][BATCH * HID];
__device__ float g_c[2][BATCH * HID];

__device__ __forceinline__ float sigmoidf_(float x) {
    return 1.0f / (1.0f + __expf(-x));
}

__global__ void init_state() {
    int i = blockIdx.x * blockDim.x + threadIdx.x;
    g_h[0][i] = 0.0f;
    g_c[0][i] = 0.0f;
}

// xg[m][n] = sum_k emb[tok(m)][k] * W_ih[n][k] + b_ih[n] + b_hh[n]
// m = t*BATCH + b, tok(m) = x[b*SEQ + t]
// Tiled fp32 GEMM: 64x64 tile, BK=16, 256 threads, 4x4 micro-tile.
__global__ void xg_gemm(const int* __restrict__ x, const float* __restrict__ emb,
                        const float* __restrict__ W_ih,
                        const float* __restrict__ b_ih, const float* __restrict__ b_hh) {
    __shared__ float As[16][64];
    __shared__ float Bs[16][64];
    __shared__ int   tok_s[64];

    const int m0  = blockIdx.y * 64;
    const int n0  = blockIdx.x * 64;
    const int tid = threadIdx.x;        // 256
    const int tx  = tid & 15, ty = tid >> 4;
    const int r   = tid >> 2, q  = tid & 3;

    if (tid < 64) {
        int m = m0 + tid;
        tok_s[tid] = x[(m & (BATCH - 1)) * SEQ + (m >> 6)];
    }
    __syncthreads();

    const size_t arow = (size_t)tok_s[r] * EMB;
    const size_t brow = (size_t)(n0 + r) * EMB;

    float acc[4][4] = {};
    for (int kt = 0; kt < EMB; kt += 16) {
        float4 av = *(const float4*)(emb  + arow + kt + q * 4);
        float4 bv = *(const float4*)(W_ih + brow + kt + q * 4);
        As[q*4+0][r] = av.x; As[q*4+1][r] = av.y; As[q*4+2][r] = av.z; As[q*4+3][r] = av.w;
        Bs[q*4+0][r] = bv.x; Bs[q*4+1][r] = bv.y; Bs[q*4+2][r] = bv.z; Bs[q*4+3][r] = bv.w;
        __syncthreads();
        #pragma unroll
        for (int k = 0; k < 16; k++) {
            float4 a = *(const float4*)&As[k][ty * 4];
            float4 b = *(const float4*)&Bs[k][tx * 4];
            acc[0][0] += a.x*b.x; acc[0][1] += a.x*b.y; acc[0][2] += a.x*b.z; acc[0][3] += a.x*b.w;
            acc[1][0] += a.y*b.x; acc[1][1] += a.y*b.y; acc[1][2] += a.y*b.z; acc[1][3] += a.y*b.w;
            acc[2][0] += a.z*b.x; acc[2][1] += a.z*b.y; acc[2][2] += a.z*b.z; acc[2][3] += a.z*b.w;
            acc[3][0] += a.w*b.x; acc[3][1] += a.w*b.y; acc[3][2] += a.w*b.z; acc[3][3] += a.w*b.w;
        }
        __syncthreads();
    }

    #pragma unroll
    for (int i = 0; i < 4; i++) {
        int m = m0 + ty * 4 + i;
        #pragma unroll
        for (int j = 0; j < 4; j++) {
            int n = n0 + tx * 4 + j;
            g_xg[(size_t)m * G4 + n] = acc[i][j] + b_ih[n] + b_hh[n];
        }
    }
}

// One LSTM step. Thread = (b, j): computes all 4 gate preactivations
// (dot(h_in[b,:], W_hh[gate*H+j,:])), then the elementwise cell update.
// Grid: (HID/16) j-tiles x (BATCH/16) b-tiles = 128 CTAs of 256 threads.
__global__ void lstm_step(int t, int cur, const float* __restrict__ W_hh) {
    const float* __restrict__ h_in = g_h[cur];
    const float* __restrict__ c_in = g_c[cur];
    float* __restrict__ h_out = g_h[cur ^ 1];
    float* __restrict__ c_out = g_c[cur ^ 1];

    const int tid = threadIdx.x;
    const int b = blockIdx.y * 16 + (tid & 15);
    const int j = blockIdx.x * 16 + (tid >> 4);

    const float4* __restrict__ h4 = (const float4*)h_in + b * (HID / 4);
    const float4* __restrict__ wi = (const float4*)W_hh + (size_t)j * (HID / 4);
    const float4* __restrict__ wf = wi + (size_t)HID * (HID / 4);
    const float4* __restrict__ wg = wf + (size_t)HID * (HID / 4);
    const float4* __restrict__ wo = wg + (size_t)HID * (HID / 4);

    float ai = 0.f, af = 0.f, ag = 0.f, ao = 0.f;
    #pragma unroll 4
    for (int k = 0; k < HID / 4; k++) {
        float4 h  = h4[k];
        float4 vi = wi[k];
        float4 vf = wf[k];
        float4 vg = wg[k];
        float4 vo = wo[k];
        ai += h.x*vi.x + h.y*vi.y + h.z*vi.z + h.w*vi.w;
        af += h.x*vf.x + h.y*vf.y + h.z*vf.z + h.w*vf.w;
        ag += h.x*vg.x + h.y*vg.y + h.z*vg.z + h.w*vg.w;
        ao += h.x*vo.x + h.y*vo.y + h.z*vo.z + h.w*vo.w;
    }

    const float* xg = g_xg + (size_t)t * BATCH * G4 + (size_t)b * G4 + j;
    float gi = sigmoidf_(ai + xg[0]);
    float gf = sigmoidf_(af + xg[HID]);
    float gg = tanhf   (ag + xg[2 * HID]);
    float go = sigmoidf_(ao + xg[3 * HID]);

    float cc = gf * c_in[b * HID + j] + gi * gg;
    float hh = go * tanhf(cc);
    h_out[b * HID + j] = hh;
    c_out[b * HID + j] = cc;
}

// Final FC: out[b][c] = h_T[b,:] . W_fc[c,:] + b_fc[c]. 64*4 = 256 threads.
__global__ void fc_kernel(const float* __restrict__ W_fc, const float* __restrict__ b_fc,
                          float* __restrict__ out) {
    int tid = threadIdx.x;         // 256
    int b = tid >> 2, c = tid & 3;
    const float4* h4 = (const float4*)(g_h[0]) + b * (HID / 4);
    const float4* w4 = (const float4*)W_fc + c * (HID / 4);
    float acc = 0.f;
    #pragma unroll 8
    for (int k = 0; k < HID / 4; k++) {
        float4 h = h4[k];
        float4 w = w4[k];
        acc += h.x*w.x + h.y*w.y + h.z*w.z + h.w*w.w;
    }
    out[b * NCLS + c] = acc + b_fc[c];
}

extern "C" void kernel_launch(void* const* d_in, const int* in_sizes, int n_in,
                              void* d_out, int out_size) {
    const int*   x    = (const int*)  d_in[0];
    const float* emb  = (const float*)d_in[1];
    const float* W_ih = (const float*)d_in[2];
    const float* W_hh = (const float*)d_in[3];
    const float* b_ih = (const float*)d_in[4];
    const float* b_hh = (const float*)d_in[5];
    const float* W_fc = (const float*)d_in[6];
    const float* b_fc = (const float*)d_in[7];
    float* out = (float*)d_out;

    init_state<<<64, 512>>>();

    dim3 g1(G4 / 64, (SEQ * BATCH) / 64);   // 32 x 512 CTAs
    xg_gemm<<<g1, 256>>>(x, emb, W_ih, b_ih, b_hh);

    for (int t = 0; t < SEQ; t++) {
        lstm_step<<<dim3(HID / 16, BATCH / 16), 256>>>(t, t & 1, W_hh);
    }
    // After step t=511 (cur=1), final h is in g_h[0].
    fc_kernel<<<1, 256>>>(W_fc, b_fc, out);
}

// round 3
// speedup vs baseline: 3.0645x; 3.0645x over previous
#include <cuda_runtime.h>
#include <math.h>

#define BATCH 64
#define SEQ   512
#define EMB   256
#define HID   512
#define G4    2048   // 4*HID
#define NCLS  4
#define NCTA  128    // persistent CTAs, one per SM (<=148)

// Scratch (allocation-free rule: __device__ globals)
__device__ float g_xg[(size_t)SEQ * G4 * BATCH];   // [t][n][b], n = gate*H + j  (256 MiB)
__device__ float g_h[2][HID * BATCH];              // [buf][j][b]  (transposed!)
__device__ unsigned int g_bar;

__device__ __forceinline__ float sigmoidf_(float x) {
    return 1.0f / (1.0f + __expf(-x));
}

__global__ void init_state() {
    int i = blockIdx.x * blockDim.x + threadIdx.x;
    g_h[0][i] = 0.0f;
    if (i == 0) g_bar = 0u;
}

// xg[t][n][b] = sum_k emb[tok(t,b)][k] * W_ih[n][k] + b_ih[n] + b_hh[n]
// Tiled fp32 GEMM: 64x64 tile, BK=16, 256 threads, 4x4 micro-tile.
// Each blockIdx.y tile covers exactly one t (64 m-rows = 64 batches of one t).
__global__ void xg_gemm(const int* __restrict__ x, const float* __restrict__ emb,
                        const float* __restrict__ W_ih,
                        const float* __restrict__ b_ih, const float* __restrict__ b_hh) {
    __shared__ float As[16][64];
    __shared__ float Bs[16][64];
    __shared__ int   tok_s[64];

    const int m0  = blockIdx.y * 64;
    const int n0  = blockIdx.x * 64;
    const int tid = threadIdx.x;        // 256
    const int tx  = tid & 15, ty = tid >> 4;
    const int r   = tid >> 2, q  = tid & 3;

    if (tid < 64) {
        int m = m0 + tid;
        tok_s[tid] = x[(m & (BATCH - 1)) * SEQ + (m >> 6)];
    }
    __syncthreads();

    const size_t arow = (size_t)tok_s[r] * EMB;
    const size_t brow = (size_t)(n0 + r) * EMB;

    float acc[4][4] = {};
    for (int kt = 0; kt < EMB; kt += 16) {
        float4 av = *(const float4*)(emb  + arow + kt + q * 4);
        float4 bv = *(const float4*)(W_ih + brow + kt + q * 4);
        As[q*4+0][r] = av.x; As[q*4+1][r] = av.y; As[q*4+2][r] = av.z; As[q*4+3][r] = av.w;
        Bs[q*4+0][r] = bv.x; Bs[q*4+1][r] = bv.y; Bs[q*4+2][r] = bv.z; Bs[q*4+3][r] = bv.w;
        __syncthreads();
        #pragma unroll
        for (int k = 0; k < 16; k++) {
            float4 a = *(const float4*)&As[k][ty * 4];
            float4 b = *(const float4*)&Bs[k][tx * 4];
            acc[0][0] += a.x*b.x; acc[0][1] += a.x*b.y; acc[0][2] += a.x*b.z; acc[0][3] += a.x*b.w;
            acc[1][0] += a.y*b.x; acc[1][1] += a.y*b.y; acc[1][2] += a.y*b.z; acc[1][3] += a.y*b.w;
            acc[2][0] += a.z*b.x; acc[2][1] += a.z*b.y; acc[2][2] += a.z*b.z; acc[2][3] += a.z*b.w;
            acc[3][0] += a.w*b.x; acc[3][1] += a.w*b.y; acc[3][2] += a.w*b.z; acc[3][3] += a.w*b.w;
        }
        __syncthreads();
    }

    // write [t][n][b] layout; within this block t is constant, b = ty*4+i.
    const int t = m0 >> 6;
    #pragma unroll
    for (int j = 0; j < 4; j++) {
        int n = n0 + tx * 4 + j;
        float bias = b_ih[n] + b_hh[n];
        float4 v = make_float4(acc[0][j] + bias, acc[1][j] + bias,
                               acc[2][j] + bias, acc[3][j] + bias);
        *(float4*)&g_xg[((size_t)t * G4 + n) * BATCH + ty * 4] = v;
    }
}

// Persistent recurrence: 128 CTAs (1/SM), each owns 4 hidden units (16 W_hh rows
// in smem). Per step: coop-load h[512][64] to smem, compute 4-gate dot products,
// elementwise update (c in registers), write h (transposed, coalesced), grid barrier.
__global__ void __launch_bounds__(256, 1)
lstm_persistent(const float* __restrict__ W_hh) {
    extern __shared__ float sm[];
    float* h_s = sm;                    // [512][64]: h_s[k*64 + b]
    float* W_s = sm + HID * BATCH;      // [16][512]: row = gate*4 + unit

    const int tid = threadIdx.x;        // 256
    const int cta = blockIdx.x;
    const int b = tid & 63;
    const int r = tid >> 6;             // local unit 0..3
    const int j0 = cta * 4;

    // One-time: load this CTA's 16 W_hh rows into smem.
    for (int row = 0; row < 16; row++) {
        int g = row >> 2, u = row & 3;
        const float* src = W_hh + (size_t)(g * HID + j0 + u) * HID;
        for (int k = tid; k < HID; k += 256)
            W_s[row * HID + k] = src[k];
    }
    float c_reg = 0.0f;
    __syncthreads();

    const float4* W4 = (const float4*)W_s;
    const float4* wi = W4 + (0 * 4 + r) * (HID / 4);
    const float4* wf = W4 + (1 * 4 + r) * (HID / 4);
    const float4* wg = W4 + (2 * 4 + r) * (HID / 4);
    const float4* wo = W4 + (3 * 4 + r) * (HID / 4);

    for (int t = 0; t < SEQ; t++) {
        const int rb = t & 1;

        // Cooperative load of h (bypass L1: other SMs wrote it).
        const float4* src = (const float4*)g_h[rb];
        float4* dst = (float4*)h_s;
        #pragma unroll
        for (int i = 0; i < 32; i++)
            dst[tid + i * 256] = __ldcg(src + tid + i * 256);
        __syncthreads();

        // Prefetch xg for this (t, b, j0+r).
        const float* xg = g_xg + ((size_t)t * G4 + (j0 + r)) * BATCH + b;
        float xi = xg[0 * HID * BATCH];
        float xf = xg[1 * HID * BATCH];
        float xG = xg[2 * HID * BATCH];
        float xo = xg[3 * HID * BATCH];

        float ai = 0.f, af = 0.f, ag = 0.f, ao = 0.f;
        const float* hb = h_s + b;
        #pragma unroll 8
        for (int k4 = 0; k4 < 128; k4++) {
            float h0 = hb[k4 * 256];
            float h1 = hb[k4 * 256 + 64];
            float h2 = hb[k4 * 256 + 128];
            float h3 = hb[k4 * 256 + 192];
            float4 vi = wi[k4], vf = wf[k4], vg = wg[k4], vo = wo[k4];
            ai += vi.x*h0 + vi.y*h1 + vi.z*h2 + vi.w*h3;
            af += vf.x*h0 + vf.y*h1 + vf.z*h2 + vf.w*h3;
            ag += vg.x*h0 + vg.y*h1 + vg.z*h2 + vg.w*h3;
            ao += vo.x*h0 + vo.y*h1 + vo.z*h2 + vo.w*h3;
        }

        float gi = sigmoidf_(ai + xi);
        float gf = sigmoidf_(af + xf);
        float gG = tanhf   (ag + xG);
        float go = sigmoidf_(ao + xo);
        c_reg = gf * c_reg + gi * gG;
        float hv = go * tanhf(c_reg);

        __stcg(&g_h[rb ^ 1][(j0 + r) * BATCH + b], hv);

        // Grid barrier (sense: monotonically increasing counter, reset per launch).
        __threadfence();
        __syncthreads();
        if (tid == 0) {
            atomicAdd(&g_bar, 1u);
            const unsigned target = (unsigned)(t + 1) * NCTA;
            while (*((volatile unsigned*)&g_bar) < target) { }
            __threadfence();
        }
        __syncthreads();
    }
}

// Final FC: out[b][c] = h_T[b,:] . W_fc[c,:] + b_fc[c].  h stored as [j][b].
__global__ void fc_kernel(const float* __restrict__ W_fc, const float* __restrict__ b_fc,
                          float* __restrict__ out) {
    int tid = threadIdx.x;         // 256
    int b = tid >> 2, c = tid & 3;
    const float* h0 = g_h[0];
    const float* w  = W_fc + c * HID;
    float acc = 0.f;
    #pragma unroll 8
    for (int k = 0; k < HID; k++)
        acc += h0[k * BATCH + b] * w[k];
    out[b * NCLS + c] = acc + b_fc[c];
}

extern "C" void kernel_launch(void* const* d_in, const int* in_sizes, int n_in,
                              void* d_out, int out_size) {
    const int*   x    = (const int*)  d_in[0];
    const float* emb  = (const float*)d_in[1];
    const float* W_ih = (const float*)d_in[2];
    const float* W_hh = (const float*)d_in[3];
    const float* b_ih = (const float*)d_in[4];
    const float* b_hh = (const float*)d_in[5];
    const float* W_fc = (const float*)d_in[6];
    const float* b_fc = (const float*)d_in[7];
    float* out = (float*)d_out;

    const int smem_bytes = (HID * BATCH + 16 * HID) * sizeof(float);  // 160 KiB
    cudaFuncSetAttribute(lstm_persistent,
                         cudaFuncAttributeMaxDynamicSharedMemorySize, smem_bytes);

    init_state<<<64, 512>>>();

    dim3 g1(G4 / 64, (SEQ * BATCH) / 64);   // 32 x 512 CTAs
    xg_gemm<<<g1, 256>>>(x, emb, W_ih, b_ih, b_hh);

    lstm_persistent<<<NCTA, 256, smem_bytes>>>(W_hh);

    fc_kernel<<<1, 256>>>(W_fc, b_fc, out);
}